// round 13
// baseline (speedup 1.0000x reference)
#include <cuda_runtime.h>

typedef unsigned long long ull;

// ---- packed f32x2 helpers ----
__device__ __forceinline__ ull pk2(float lo, float hi) {
    ull r; asm("mov.b64 %0, {%1, %2};" : "=l"(r) : "f"(lo), "f"(hi)); return r;
}
__device__ __forceinline__ ull bc2(float v) { return pk2(v, v); }
__device__ __forceinline__ void upk2(ull r, float& lo, float& hi) {
    asm("mov.b64 {%0, %1}, %2;" : "=f"(lo), "=f"(hi) : "l"(r));
}
__device__ __forceinline__ ull fma2(ull a, ull b, ull c) {
    ull d; asm("fma.rn.f32x2 %0, %1, %2, %3;" : "=l"(d) : "l"(a), "l"(b), "l"(c)); return d;
}
__device__ __forceinline__ ull add2(ull a, ull b) {
    ull d; asm("add.rn.f32x2 %0, %1, %2;" : "=l"(d) : "l"(a), "l"(b)); return d;
}
__device__ __forceinline__ ull mul2(ull a, ull b) {
    ull d; asm("mul.rn.f32x2 %0, %1, %2;" : "=l"(d) : "l"(a), "l"(b)); return d;
}
__device__ __forceinline__ float ex2a(float x) {
    float y; asm("ex2.approx.f32 %0, %1;" : "=f"(y) : "f"(x)); return y;
}
__device__ __forceinline__ float rcpa(float x) {
    float y; asm("rcp.approx.f32 %0, %1;" : "=f"(y) : "f"(x)); return y;
}

// Shapes: b=4, c=16, m=8, h=w=64, O=64.
// CTA: 64 threads = sp(4) x ol(16), covering o-quarter oq = blockIdx.x&3.
// Full j=16 per thread, NO shuffles (R10 main loop). 6 CTAs resident/SM.
// Smem (floats):
//   qs  [0,4160)      q[i][ol*16+pix], i-stride 260
//   xs  [4160,6272)   x[ch][m*16+pix], ch-stride 132
//   res [6272,6528)   0.125*sum_m x, [i*16+pix]
//   wqs [6528,6656)   wq(this quarter) * 0.125*log2(e), [ol*8+m]
//   wkp [6656,7232)   ull j-pairs [r2*9+m], rows (2r2,2r2+1), all 64 rows
//   wvp [7232,7808)   same for wv
#define QS_I 260
#define XS_CH 132
#define SMEM_FLOATS 7808
#define SMEM_BYTES (SMEM_FLOATS * 4)

__global__ __launch_bounds__(64, 6) void adapt_attn(
    const float* __restrict__ x,
    const float* __restrict__ wq,
    const float* __restrict__ wk,
    const float* __restrict__ wv,
    float* __restrict__ out)
{
    extern __shared__ __align__(16) float smem[];
    float* qs  = smem;
    float* xs  = smem + 4160;
    float* res = smem + 6272;
    float* wqs = smem + 6528;
    ull*   wkp = (ull*)(smem + 6656);
    ull*   wvp = (ull*)(smem + 7232);

    const int t   = threadIdx.x;
    const int bx  = blockIdx.x;   // 0..31
    const int lwg = bx >> 2;      // 0..7
    const int oq  = bx & 3;       // o-quarter
    const int lh  = blockIdx.y;   // 0..31
    const int b   = blockIdx.z;   // 0..3
    const int hh0 = 2 * lh, ww0 = 8 * lwg;

    // ---- stage x tile (512 float4, 8 per thread): pix = sp*4 + (hhi*2+col) ----
#pragma unroll
    for (int it = 0; it < 8; ++it) {
        int idx = t + it * 64;
        int q4  = idx & 1;
        int hhi = (idx >> 1) & 1;
        int m   = (idx >> 2) & 7;
        int ch  = idx >> 5;
        const float4 v = *reinterpret_cast<const float4*>(
            x + ((b * 16 + ch) * 8 + m) * 4096 + (hh0 + hhi) * 64 + ww0 + 4 * q4);
        float* dst = xs + ch * XS_CH + m * 16 + 8 * q4 + 2 * hhi;
        *reinterpret_cast<ull*>(dst)     = pk2(v.x, v.y);
        *reinterpret_cast<ull*>(dst + 4) = pk2(v.z, v.w);
    }
    // ---- stage weights ----
#pragma unroll
    for (int it = 0; it < 2; ++it) {       // wqs: 128 entries for this quarter
        int idx = t + it * 64;
        int m = idx & 7, r = idx >> 3;      // r = ol 0..15
        wqs[idx] = wq[(oq * 16 + r) * 8 + m] * 0.18033688011112042f; // 0.125*log2e
    }
#pragma unroll
    for (int it = 0; it < 4; ++it) {       // wkp/wvp: all 32 row-pairs
        int idx = t + it * 64;              // 0..255
        int m = idx & 7, r2 = idx >> 3;     // r2 = 0..31
        wkp[r2 * 9 + m] = pk2(wk[(2 * r2) * 8 + m], wk[(2 * r2 + 1) * 8 + m]);
        wvp[r2 * 9 + m] = pk2(wv[(2 * r2) * 8 + m], wv[(2 * r2 + 1) * 8 + m]);
    }
    __syncthreads();

    // ---- res = 0.125 * sum_m x (4 elems per thread) ----
#pragma unroll
    for (int it = 0; it < 4; ++it) {
        int idx = t + it * 64;
        int i = idx >> 4, pix = idx & 15;
        const float* xr = xs + i * XS_CH + pix;
        float s = 0.f;
#pragma unroll
        for (int m = 0; m < 8; ++m) s += xr[m * 16];
        res[i * 16 + pix] = 0.125f * s;
    }

    // ---- cooperative q, loop-interchanged: i = t&15, og = t>>4 -> 4 ol ----
    {
        int i = t & 15, og = t >> 4;        // og 0..3 -> ol = og*4 .. og*4+3
        const ull* xr = reinterpret_cast<const ull*>(xs + i * XS_CH);
        const float* wo = wqs + (og * 4) * 8;
        ull acc[4][8];
#pragma unroll
        for (int n = 0; n < 4; ++n)
#pragma unroll
            for (int p = 0; p < 8; ++p) acc[n][p] = 0ull;
#pragma unroll
        for (int m = 0; m < 8; ++m) {
            ull xm[8];
#pragma unroll
            for (int p = 0; p < 8; ++p) xm[p] = xr[m * 8 + p];
#pragma unroll
            for (int n = 0; n < 4; ++n) {
                ull wb = bc2(wo[n * 8 + m]);
#pragma unroll
                for (int p = 0; p < 8; ++p)
                    acc[n][p] = fma2(wb, xm[p], acc[n][p]);
            }
        }
#pragma unroll
        for (int n = 0; n < 4; ++n) {
            ull* qd = reinterpret_cast<ull*>(qs + i * QS_I + (og * 4 + n) * 16);
#pragma unroll
            for (int p = 0; p < 8; ++p) qd[p] = acc[n][p];
        }
    }

    // ---- per-thread k/v (full j = 16, packed over j-pairs) ----
    const int sp = t & 3;
    const int ol = t >> 2;                 // 0..15
    const int o  = oq * 16 + ol;           // global o
    const int ck = o >> 2;                 // x channel (o&3 == ol&3)

    ull kq[8][4], vq[8][4];
#pragma unroll
    for (int j2 = 0; j2 < 8; ++j2)
#pragma unroll
        for (int p = 0; p < 4; ++p) { kq[j2][p] = 0ull; vq[j2][p] = 0ull; }
    {
        const ull* wkg = wkp + ((ol & 3) * 8) * 9;
        const ull* wvg = wvp + ((ol & 3) * 8) * 9;
        const float* xck = xs + ck * XS_CH;
#pragma unroll
        for (int m = 0; m < 8; ++m) {
            float4 xv = *reinterpret_cast<const float4*>(xck + m * 16 + sp * 4);
            ull xb0 = bc2(xv.x), xb1 = bc2(xv.y), xb2 = bc2(xv.z), xb3 = bc2(xv.w);
#pragma unroll
            for (int j2 = 0; j2 < 8; ++j2) {
                ull wkv = wkg[j2 * 9 + m];
                kq[j2][0] = fma2(wkv, xb0, kq[j2][0]);
                kq[j2][1] = fma2(wkv, xb1, kq[j2][1]);
                kq[j2][2] = fma2(wkv, xb2, kq[j2][2]);
                kq[j2][3] = fma2(wkv, xb3, kq[j2][3]);
                ull wvv = wvg[j2 * 9 + m];
                vq[j2][0] = fma2(wvv, xb0, vq[j2][0]);
                vq[j2][1] = fma2(wvv, xb1, vq[j2][1]);
                vq[j2][2] = fma2(wvv, xb2, vq[j2][2]);
                vq[j2][3] = fma2(wvv, xb3, vq[j2][3]);
            }
        }
    }
    __syncthreads();   // qs/res complete before main loop

    const float* qso = qs + ol * 16 + sp * 4;
    const ulonglong2* resv = reinterpret_cast<const ulonglong2*>(res + sp * 4);
    float* op = out + ((b * 16) * 64 + o) * 4096 + hh0 * 64 + ww0 + 2 * sp;

    // ==== main loop (R10): q prefetch, no shuffles, res as single LDS.128 ====
    float4 qv = *reinterpret_cast<const float4*>(qso);
#pragma unroll 1
    for (int i = 0; i < 16; ++i) {
        float4 qvn = *reinterpret_cast<const float4*>(qso + ((i + 1) & 15) * QS_I);

        ull qb0 = bc2(qv.x), qb1 = bc2(qv.y), qb2 = bc2(qv.z), qb3 = bc2(qv.w);

        // att (pre-scaled) -> e = 2^att packed over j-pairs (no max: |att| << 30)
        ull ep[8];
#pragma unroll
        for (int j2 = 0; j2 < 8; ++j2) {
            ull at = mul2(qb0, kq[j2][0]);
            at = fma2(qb1, kq[j2][1], at);
            at = fma2(qb2, kq[j2][2], at);
            at = fma2(qb3, kq[j2][3], at);
            float alo, ahi; upk2(at, alo, ahi);
            ep[j2] = pk2(ex2a(alo), ex2a(ahi));
        }

        // softmax denominator (packed tree + 1 horizontal)
        ull s = add2(add2(add2(ep[0], ep[1]), add2(ep[2], ep[3])),
                     add2(add2(ep[4], ep[5]), add2(ep[6], ep[7])));
        float slo, shi; upk2(s, slo, shi);
        ull invb = bc2(rcpa(slo + shi));

        // out[p] = horiz( sum_j2 ep[j2] (x) vq[j2][p] )
        ull a0 = mul2(ep[0], vq[0][0]);
        ull a1 = mul2(ep[0], vq[0][1]);
        ull a2 = mul2(ep[0], vq[0][2]);
        ull a3 = mul2(ep[0], vq[0][3]);
#pragma unroll
        for (int j2 = 1; j2 < 8; ++j2) {
            a0 = fma2(ep[j2], vq[j2][0], a0);
            a1 = fma2(ep[j2], vq[j2][1], a1);
            a2 = fma2(ep[j2], vq[j2][2], a2);
            a3 = fma2(ep[j2], vq[j2][3], a3);
        }
        float e0, e1, e2, e3, d0, d1, d2, d3;
        upk2(a0, e0, d0); upk2(a1, e1, d1);
        upk2(a2, e2, d2); upk2(a3, e3, d3);

        // FIXED: ulonglong2 element = 4 floats, so one i-step (16 floats) = index +4
        ulonglong2 rv = resv[i * 4];        // one LDS.128: both row-residuals
        ull f0 = fma2(pk2(e0 + d0, e1 + d1), invb, rv.x);   // row hh0
        ull f1 = fma2(pk2(e2 + d2, e3 + d3), invb, rv.y);   // row hh0+1
        *reinterpret_cast<ull*>(op)      = f0;
        *reinterpret_cast<ull*>(op + 64) = f1;
        op += 64 * 4096;

        qv = qvn;
    }
}

extern "C" void kernel_launch(void* const* d_in, const int* in_sizes, int n_in,
                              void* d_out, int out_size) {
    const float* x  = (const float*)d_in[0];
    const float* wq = (const float*)d_in[1];
    const float* wk = (const float*)d_in[2];
    const float* wv = (const float*)d_in[3];
    // d_in[4] (w_p): positional term is constant over the softmax axis -> cancels exactly.
    static int attr_set = 0;
    if (!attr_set) {
        cudaFuncSetAttribute(adapt_attn, cudaFuncAttributeMaxDynamicSharedMemorySize,
                             SMEM_BYTES);
        attr_set = 1;
    }
    dim3 grid(32, 32, 4);   // (lwg*4+oq, lh, b)
    adapt_attn<<<grid, 64, SMEM_BYTES>>>(x, wq, wk, wv, (float*)d_out);
}

// round 14
// speedup vs baseline: 1.0799x; 1.0799x over previous
#include <cuda_runtime.h>

typedef unsigned long long ull;

// ---- packed f32x2 helpers ----
__device__ __forceinline__ ull pk2(float lo, float hi) {
    ull r; asm("mov.b64 %0, {%1, %2};" : "=l"(r) : "f"(lo), "f"(hi)); return r;
}
__device__ __forceinline__ ull bc2(float v) { return pk2(v, v); }
__device__ __forceinline__ void upk2(ull r, float& lo, float& hi) {
    asm("mov.b64 {%0, %1}, %2;" : "=f"(lo), "=f"(hi) : "l"(r));
}
__device__ __forceinline__ ull fma2(ull a, ull b, ull c) {
    ull d; asm("fma.rn.f32x2 %0, %1, %2, %3;" : "=l"(d) : "l"(a), "l"(b), "l"(c)); return d;
}
__device__ __forceinline__ ull add2(ull a, ull b) {
    ull d; asm("add.rn.f32x2 %0, %1, %2;" : "=l"(d) : "l"(a), "l"(b)); return d;
}
__device__ __forceinline__ ull mul2(ull a, ull b) {
    ull d; asm("mul.rn.f32x2 %0, %1, %2;" : "=l"(d) : "l"(a), "l"(b)); return d;
}
__device__ __forceinline__ float ex2a(float x) {
    float y; asm("ex2.approx.f32 %0, %1;" : "=f"(y) : "f"(x)); return y;
}
__device__ __forceinline__ float rcpa(float x) {
    float y; asm("rcp.approx.f32 %0, %1;" : "=f"(y) : "f"(x)); return y;
}

// Shapes: b=4, c=16, m=8, h=w=64, O=64.
// CTA: 128 threads = sp(2) x o(64), covering a 2-row x 4-col pixel half-tile.
// Pixel-split: NOTHING duplicated across CTAs (x staged once chip-wide).
// Full j=16 per thread, NO shuffles (R10 main loop). 3 CTAs resident/SM.
// Thread: sp = t&1, o = t>>1.
// Smem (floats):
//   qs  [0,8256)       q[i][o*8+pix], i-stride 516
//   xs  [8256,9344)    x[ch][m*8+pix], ch-stride 68
//   res [9344,9472)    0.125*sum_m x, [i*8+pix]
//   wqs [9472,9984)    wq * 0.125*log2(e), [o*8+m], all 64 o
//   wkp [9984,10560)   ull j-pairs [r2*9+m], rows (2r2,2r2+1)
//   wvp [10560,11136)  same for wv
#define QS_I 516
#define XS_CH 68
#define SMEM_FLOATS 11136
#define SMEM_BYTES (SMEM_FLOATS * 4)

__global__ __launch_bounds__(128, 3) void adapt_attn(
    const float* __restrict__ x,
    const float* __restrict__ wq,
    const float* __restrict__ wk,
    const float* __restrict__ wv,
    float* __restrict__ out)
{
    extern __shared__ __align__(16) float smem[];
    float* qs  = smem;
    float* xs  = smem + 8256;
    float* res = smem + 9344;
    float* wqs = smem + 9472;
    ull*   wkp = (ull*)(smem + 9984);
    ull*   wvp = (ull*)(smem + 10560);

    const int t   = threadIdx.x;
    const int wwg = blockIdx.x;   // 0..15  (4-col groups)
    const int lh  = blockIdx.y;   // 0..31
    const int b   = blockIdx.z;   // 0..3
    const int hh0 = 2 * lh, ww0 = 4 * wwg;

    // ---- stage x half-tile (256 float4, 2 per thread) ----
    // pix = sp*4 + hhi*2 + col; float4 covers the 4 tile columns:
    // (v.x,v.y) -> sp=0 cols {0,1}, (v.z,v.w) -> sp=1 cols {0,1}
#pragma unroll
    for (int it = 0; it < 2; ++it) {
        int idx = t + it * 128;             // 0..255
        int hhi = idx & 1;
        int m   = (idx >> 1) & 7;
        int ch  = idx >> 4;
        const float4 v = *reinterpret_cast<const float4*>(
            x + ((b * 16 + ch) * 8 + m) * 4096 + (hh0 + hhi) * 64 + ww0);
        float* dst = xs + ch * XS_CH + m * 8 + 2 * hhi;
        *reinterpret_cast<ull*>(dst)     = pk2(v.x, v.y);   // sp=0
        *reinterpret_cast<ull*>(dst + 4) = pk2(v.z, v.w);   // sp=1
    }
    // ---- stage weights ----
#pragma unroll
    for (int it = 0; it < 4; ++it) {        // wqs: all 512 entries
        int idx = t + it * 128;
        wqs[idx] = wq[idx] * 0.18033688011112042f;  // 0.125 * log2(e)
    }
#pragma unroll
    for (int it = 0; it < 2; ++it) {        // wkp/wvp: 32 row-pairs x 8 m
        int idx = t + it * 128;             // 0..255
        int m = idx & 7, r2 = idx >> 3;     // r2 = 0..31 -> rows (2r2, 2r2+1)
        wkp[r2 * 9 + m] = pk2(wk[(2 * r2) * 8 + m], wk[(2 * r2 + 1) * 8 + m]);
        wvp[r2 * 9 + m] = pk2(wv[(2 * r2) * 8 + m], wv[(2 * r2 + 1) * 8 + m]);
    }
    __syncthreads();

    // ---- res = 0.125 * sum_m x (1 elem per thread: 16 i x 8 pix) ----
    {
        int i = t >> 3, pix = t & 7;
        const float* xr = xs + i * XS_CH + pix;
        float s = 0.f;
#pragma unroll
        for (int m = 0; m < 8; ++m) s += xr[m * 8];
        res[i * 8 + pix] = 0.125f * s;
    }

    // ---- cooperative q, loop-interchanged: (i = t&15, og = t>>4) -> 8 o ----
    {
        int i = t & 15, og = t >> 4;        // og 0..7 -> o = og*8 .. og*8+7
        const ull* xr = reinterpret_cast<const ull*>(xs + i * XS_CH);
        const float* wo = wqs + (og * 8) * 8;
        ull acc[8][4];
#pragma unroll
        for (int n = 0; n < 8; ++n)
#pragma unroll
            for (int p = 0; p < 4; ++p) acc[n][p] = 0ull;
#pragma unroll
        for (int m = 0; m < 8; ++m) {
            ull xm[4];
#pragma unroll
            for (int p = 0; p < 4; ++p) xm[p] = xr[m * 4 + p];
#pragma unroll
            for (int n = 0; n < 8; ++n) {
                ull wb = bc2(wo[n * 8 + m]);
#pragma unroll
                for (int p = 0; p < 4; ++p)
                    acc[n][p] = fma2(wb, xm[p], acc[n][p]);
            }
        }
#pragma unroll
        for (int n = 0; n < 8; ++n) {
            ull* qd = reinterpret_cast<ull*>(qs + i * QS_I + (og * 8 + n) * 8);
#pragma unroll
            for (int p = 0; p < 4; ++p) qd[p] = acc[n][p];
        }
    }

    // ---- per-thread k/v (full j = 16, packed over j-pairs) ----
    const int sp = t & 1;
    const int o  = t >> 1;                 // 0..63
    const int ck = o >> 2;                 // x channel 0..15

    ull kq[8][4], vq[8][4];
#pragma unroll
    for (int j2 = 0; j2 < 8; ++j2)
#pragma unroll
        for (int p = 0; p < 4; ++p) { kq[j2][p] = 0ull; vq[j2][p] = 0ull; }
    {
        const ull* wkg = wkp + ((o & 3) * 8) * 9;
        const ull* wvg = wvp + ((o & 3) * 8) * 9;
        const float* xck = xs + ck * XS_CH;
#pragma unroll
        for (int m = 0; m < 8; ++m) {
            float4 xv = *reinterpret_cast<const float4*>(xck + m * 8 + sp * 4);
            ull xb0 = bc2(xv.x), xb1 = bc2(xv.y), xb2 = bc2(xv.z), xb3 = bc2(xv.w);
#pragma unroll
            for (int j2 = 0; j2 < 8; ++j2) {
                ull wkv = wkg[j2 * 9 + m];
                kq[j2][0] = fma2(wkv, xb0, kq[j2][0]);
                kq[j2][1] = fma2(wkv, xb1, kq[j2][1]);
                kq[j2][2] = fma2(wkv, xb2, kq[j2][2]);
                kq[j2][3] = fma2(wkv, xb3, kq[j2][3]);
                ull wvv = wvg[j2 * 9 + m];
                vq[j2][0] = fma2(wvv, xb0, vq[j2][0]);
                vq[j2][1] = fma2(wvv, xb1, vq[j2][1]);
                vq[j2][2] = fma2(wvv, xb2, vq[j2][2]);
                vq[j2][3] = fma2(wvv, xb3, vq[j2][3]);
            }
        }
    }
    __syncthreads();   // qs/res complete before main loop

    const float* qso = qs + o * 8 + sp * 4;
    const ulonglong2* resv = reinterpret_cast<const ulonglong2*>(res + sp * 4);
    float* op = out + ((b * 16) * 64 + o) * 4096 + hh0 * 64 + ww0 + 2 * sp;

    // ==== main loop (R10): q prefetch, no shuffles, res as single LDS.128 ====
    float4 qv = *reinterpret_cast<const float4*>(qso);
#pragma unroll 1
    for (int i = 0; i < 16; ++i) {
        float4 qvn = *reinterpret_cast<const float4*>(qso + ((i + 1) & 15) * QS_I);

        ull qb0 = bc2(qv.x), qb1 = bc2(qv.y), qb2 = bc2(qv.z), qb3 = bc2(qv.w);

        // att (pre-scaled) -> e = 2^att packed over j-pairs (no max: |att| << 30)
        ull ep[8];
#pragma unroll
        for (int j2 = 0; j2 < 8; ++j2) {
            ull at = mul2(qb0, kq[j2][0]);
            at = fma2(qb1, kq[j2][1], at);
            at = fma2(qb2, kq[j2][2], at);
            at = fma2(qb3, kq[j2][3], at);
            float alo, ahi; upk2(at, alo, ahi);
            ep[j2] = pk2(ex2a(alo), ex2a(ahi));
        }

        // softmax denominator (packed tree + 1 horizontal)
        ull s = add2(add2(add2(ep[0], ep[1]), add2(ep[2], ep[3])),
                     add2(add2(ep[4], ep[5]), add2(ep[6], ep[7])));
        float slo, shi; upk2(s, slo, shi);
        ull invb = bc2(rcpa(slo + shi));

        // out[p] = horiz( sum_j2 ep[j2] (x) vq[j2][p] )
        ull a0 = mul2(ep[0], vq[0][0]);
        ull a1 = mul2(ep[0], vq[0][1]);
        ull a2 = mul2(ep[0], vq[0][2]);
        ull a3 = mul2(ep[0], vq[0][3]);
#pragma unroll
        for (int j2 = 1; j2 < 8; ++j2) {
            a0 = fma2(ep[j2], vq[j2][0], a0);
            a1 = fma2(ep[j2], vq[j2][1], a1);
            a2 = fma2(ep[j2], vq[j2][2], a2);
            a3 = fma2(ep[j2], vq[j2][3], a3);
        }
        float e0, e1, e2, e3, d0, d1, d2, d3;
        upk2(a0, e0, d0); upk2(a1, e1, d1);
        upk2(a2, e2, d2); upk2(a3, e3, d3);

        // res i-stride = 8 floats = 2 ulonglong2 elements
        ulonglong2 rv = resv[i * 2];        // one LDS.128: both row-residuals
        ull f0 = fma2(pk2(e0 + d0, e1 + d1), invb, rv.x);   // row hh0
        ull f1 = fma2(pk2(e2 + d2, e3 + d3), invb, rv.y);   // row hh0+1
        *reinterpret_cast<ull*>(op)      = f0;
        *reinterpret_cast<ull*>(op + 64) = f1;
        op += 64 * 4096;

        qv = qvn;
    }
}

extern "C" void kernel_launch(void* const* d_in, const int* in_sizes, int n_in,
                              void* d_out, int out_size) {
    const float* x  = (const float*)d_in[0];
    const float* wq = (const float*)d_in[1];
    const float* wk = (const float*)d_in[2];
    const float* wv = (const float*)d_in[3];
    // d_in[4] (w_p): positional term is constant over the softmax axis -> cancels exactly.
    static int attr_set = 0;
    if (!attr_set) {
        cudaFuncSetAttribute(adapt_attn, cudaFuncAttributeMaxDynamicSharedMemorySize,
                             SMEM_BYTES);
        attr_set = 1;
    }
    dim3 grid(16, 32, 4);   // (wwg, lh, b)
    adapt_attn<<<grid, 128, SMEM_BYTES>>>(x, wq, wk, wv, (float*)d_out);
}